// round 1
// baseline (speedup 1.0000x reference)
#include <cuda_runtime.h>
#include <cuda_bf16.h>
#include <cstdint>

// ---------------- static scratch (no allocations allowed) ----------------
#define FMP   40
#define NPIX  1600            // 40*40
#define PADW  42
#define PADPP 1764            // 42*42

__device__ float g_padA[1024 * PADPP];   // padded c5
__device__ float g_padB[1024 * PADPP];   // padded conv1 out
__device__ float g_padC[1280 * PADPP];   // padded concat (reorg 0..255, conv2 256..1279)
__device__ float g_p5b [1024 * NPIX];    // conv3 out (plain)
__device__ float g_pred[ 125 * NPIX];    // pred conv out
__device__ float g_scores[160000];       // 1600 px * 100
__device__ float g_segmax[1600];

__constant__ float c_aw[5] = {1.19f, 2.79f, 4.53f, 8.06f, 10.32f};
__constant__ float c_ah[5] = {1.98f, 4.59f, 8.92f, 5.29f, 10.65f};

// ---------------- packed fp32 FMA (sm_103a f32x2) ----------------
__device__ __forceinline__ void ffma2(float2& d, const float2& a, const float2& b) {
    unsigned long long&       du = reinterpret_cast<unsigned long long&>(d);
    const unsigned long long& au = reinterpret_cast<const unsigned long long&>(a);
    const unsigned long long& bu = reinterpret_cast<const unsigned long long&>(b);
    asm("fma.rn.f32x2 %0, %1, %2, %0;" : "+l"(du) : "l"(au), "l"(bu));
}

// ---------------- pad copy: (C,40,40) -> (C,42,42) interior ----------------
__global__ void pad_input(const float* __restrict__ src, float* __restrict__ dst, int C) {
    int idx = blockIdx.x * 256 + threadIdx.x;
    if (idx >= C * NPIX) return;
    int c = idx / NPIX, p = idx - c * NPIX;
    int y = p / FMP, x = p - y * FMP;
    dst[c * PADPP + (y + 1) * PADW + (x + 1)] = src[idx];
}

// ---------------- 3x3 conv as implicit GEMM, fused BN + leaky ReLU ----------
// out[oc][p] = lrelu(scale[oc]*sum + shift[oc]); M=1024, N=1600, K=Cin*9
// BM=BN=64, BK=16, 64 threads, 8x8 per thread, m packed into f32x2 pairs.
__global__ void __launch_bounds__(64, 8) conv3x3_gemm(
    const float* __restrict__ W, const float* __restrict__ padIn, int Cin,
    const float* __restrict__ scale, const float* __restrict__ shift,
    float* __restrict__ outPlain, float* __restrict__ outPad, int chanOff)
{
    __shared__ float As[16][64];   // [kk][mm]
    __shared__ float Bs[16][64];   // [kk][nn]

    const int t  = threadIdx.x;          // 0..63
    const int m0 = blockIdx.y * 64;
    const int n0 = blockIdx.x * 64;
    const int K  = Cin * 9;

    // B-load state: this thread owns column nn = t for all kk (k = k0 + kk)
    const int nn = t;
    const int p  = n0 + nn;              // pixel, < 1600
    const int py = p / FMP, px = p - py * FMP;
    const float* bsrc = padIn + (py * PADW + px);  // top-left of receptive field in padded coords
    int icoff = 0;   // ic * 1764
    int r     = 0;   // k % 9
    int roff  = 0;   // (r/3)*42 + r%3

    float2 acc[4][8];
    #pragma unroll
    for (int q = 0; q < 4; q++)
        #pragma unroll
        for (int j = 0; j < 8; j++) acc[q][j] = make_float2(0.f, 0.f);

    const int tm = t >> 3;   // 0..7
    const int tn = t & 7;    // 0..7

    for (int k0 = 0; k0 < K; k0 += 16) {
        // load A tile 64x16, store transposed
        #pragma unroll
        for (int u = 0; u < 4; u++) {
            int idx = t + 64 * u;
            int mm  = idx >> 2;
            int kk4 = (idx & 3) << 2;
            const float4 v = *reinterpret_cast<const float4*>(
                W + (size_t)(m0 + mm) * K + (k0 + kk4));
            As[kk4 + 0][mm] = v.x; As[kk4 + 1][mm] = v.y;
            As[kk4 + 2][mm] = v.z; As[kk4 + 3][mm] = v.w;
        }
        // load B tile 16x64 (implicit im2col, incremental indices)
        #pragma unroll
        for (int j = 0; j < 16; j++) {
            Bs[j][nn] = bsrc[icoff + roff];
            r++; roff++;
            if (r == 9)                { r = 0; roff = 0; icoff += PADPP; }
            else if (r == 3 || r == 6) { roff += 39; }
        }
        __syncthreads();

        #pragma unroll
        for (int kk = 0; kk < 16; kk++) {
            const float4 a0 = *reinterpret_cast<const float4*>(&As[kk][tm * 8]);
            const float4 a1 = *reinterpret_cast<const float4*>(&As[kk][tm * 8 + 4]);
            const float4 b0 = *reinterpret_cast<const float4*>(&Bs[kk][tn * 8]);
            const float4 b1 = *reinterpret_cast<const float4*>(&Bs[kk][tn * 8 + 4]);
            float2 ap[4] = { make_float2(a0.x, a0.y), make_float2(a0.z, a0.w),
                             make_float2(a1.x, a1.y), make_float2(a1.z, a1.w) };
            float  bv[8] = { b0.x, b0.y, b0.z, b0.w, b1.x, b1.y, b1.z, b1.w };
            float2 bs[8];
            #pragma unroll
            for (int j = 0; j < 8; j++) bs[j] = make_float2(bv[j], bv[j]);
            #pragma unroll
            for (int q = 0; q < 4; q++)
                #pragma unroll
                for (int j = 0; j < 8; j++)
                    ffma2(acc[q][j], ap[q], bs[j]);
        }
        __syncthreads();
    }

    // epilogue: BN + leaky ReLU, write plain or padded layout
    #pragma unroll
    for (int q = 0; q < 4; q++) {
        #pragma unroll
        for (int h = 0; h < 2; h++) {
            const int oc = m0 + tm * 8 + q * 2 + h;
            const float sc = scale[oc], sh = shift[oc];
            #pragma unroll
            for (int j = 0; j < 8; j++) {
                float v = (h ? acc[q][j].y : acc[q][j].x);
                v = v * sc + sh;
                v = v > 0.f ? v : 0.1f * v;
                const int pp = n0 + tn * 8 + j;
                if (outPad) {
                    int y = pp / FMP, x = pp - y * FMP;
                    outPad[(size_t)(chanOff + oc) * PADPP + (y + 1) * PADW + (x + 1)] = v;
                } else {
                    outPlain[(size_t)oc * NPIX + pp] = v;
                }
            }
        }
    }
}

// ---------------- reorg path: 1x1 conv (64,512) + BN + lrelu + reorg scatter --
__global__ void __launch_bounds__(256) reorg_conv(
    const float* __restrict__ c4, const float* __restrict__ wr,
    const float* __restrict__ sr, const float* __restrict__ br,
    float* __restrict__ padC)
{
    const int t  = threadIdx.x;
    const int c  = t & 63;
    const int pp = t >> 6;
    const int p  = blockIdx.x * 4 + pp;     // 0..6399 over 80x80
    const float* wrow = wr + c * 512;
    const float* xp   = c4 + p;
    float acc = 0.f;
    #pragma unroll 8
    for (int ic = 0; ic < 512; ic++)
        acc += wrow[ic] * xp[(size_t)ic * 6400];
    float v = acc * sr[c] + br[c];
    v = v > 0.f ? v : 0.1f * v;
    const int y80 = p / 80, x80 = p - y80 * 80;
    const int hi = y80 >> 1, wi = x80 >> 1;
    const int q  = (y80 & 1) * 2 + (x80 & 1);
    padC[(size_t)(q * 64 + c) * PADPP + (hi + 1) * PADW + (wi + 1)] = v;
}

// ---------------- pred: 1x1 conv (125,1024) + bias ----------------
__global__ void __launch_bounds__(256) pred_conv(
    const float* __restrict__ p5b, const float* __restrict__ wp,
    const float* __restrict__ bp, float* __restrict__ pred)
{
    const int t  = threadIdx.x;
    const int oc = t & 127;
    const int pp = t >> 7;
    const int p  = blockIdx.x * 2 + pp;
    const bool act = (oc < 125);
    const float* wrow = wp + (size_t)(act ? oc : 0) * 1024;
    float acc = 0.f;
    #pragma unroll 8
    for (int ic = 0; ic < 1024; ic++)
        acc += wrow[ic] * p5b[(size_t)ic * NPIX + p];
    if (act) pred[(size_t)oc * NPIX + p] = acc + bp[oc];
}

// ---------------- scores: sigmoid(conf)*softmax(cls) + segment max ----------
__global__ void __launch_bounds__(128) score_kernel(
    const float* __restrict__ pred, float* __restrict__ scores,
    float* __restrict__ segmax)
{
    const int p = blockIdx.x;
    const int t = threadIdx.x;
    __shared__ float sv[125];
    __shared__ float red[128];
    if (t < 125) sv[t] = pred[(size_t)t * NPIX + p];
    __syncthreads();

    float sc = -1.0f;
    if (t < 100) {
        const int a = t / 20, c = t - (t / 20) * 20;
        const float* cb = &sv[5 + a * 20];
        float m = cb[0];
        #pragma unroll
        for (int k = 1; k < 20; k++) m = fmaxf(m, cb[k]);
        float sum = 0.f;
        #pragma unroll
        for (int k = 0; k < 20; k++) sum += expf(cb[k] - m);
        const float e   = expf(cb[c] - m);
        const float sig = 1.f / (1.f + expf(-sv[a]));
        sc = sig * (e / sum);
        scores[p * 100 + t] = sc;
    }
    red[t] = sc;
    __syncthreads();
    for (int s = 64; s > 0; s >>= 1) {
        if (t < s) red[t] = fmaxf(red[t], red[t + s]);
        __syncthreads();
    }
    if (t == 0) segmax[p] = red[0];
}

// ---------------- top-100 + decode + greedy NMS + outputs (one block) ------
__global__ void __launch_bounds__(256) finalize_kernel(
    float* __restrict__ scores, const float* __restrict__ segmax_g,
    const float* __restrict__ pred, float* __restrict__ out)
{
    __shared__ float smax[1600];
    __shared__ float rv[256];
    __shared__ int   ri[256];
    __shared__ float tScore[100];
    __shared__ int   tIdx[100];
    __shared__ float bx1[100], by1[100], bx2[100], by2[100], bar[100];
    __shared__ int   lab[100];
    __shared__ int   keep[100];

    const int t = threadIdx.x;
    for (int i = t; i < 1600; i += 256) smax[i] = segmax_g[i];
    __syncthreads();

    for (int it = 0; it < 100; it++) {
        // argmax over segment maxima (tie -> lowest index, matching lax.top_k)
        float bv = -1e30f; int bi = 1 << 30;
        for (int i = t; i < 1600; i += 256) {
            float v = smax[i];
            if (v > bv) { bv = v; bi = i; }
        }
        rv[t] = bv; ri[t] = bi;
        __syncthreads();
        for (int s = 128; s > 0; s >>= 1) {
            if (t < s) {
                float v2 = rv[t + s]; int i2 = ri[t + s];
                if (v2 > rv[t] || (v2 == rv[t] && i2 < ri[t])) { rv[t] = v2; ri[t] = i2; }
            }
            __syncthreads();
        }
        const int seg = ri[0];
        __syncthreads();

        // argmax within the 100-wide segment
        float ev = -1e30f; int ei = 1 << 30;
        if (t < 100) { ev = scores[seg * 100 + t]; ei = t; }
        rv[t] = ev; ri[t] = ei;
        __syncthreads();
        for (int s = 128; s > 0; s >>= 1) {
            if (t < s) {
                float v2 = rv[t + s]; int i2 = ri[t + s];
                if (v2 > rv[t] || (v2 == rv[t] && i2 < ri[t])) { rv[t] = v2; ri[t] = i2; }
            }
            __syncthreads();
        }
        if (t == 0) {
            const int g = seg * 100 + ri[0];
            tIdx[it] = g; tScore[it] = rv[0];
            scores[g] = -1.0f;
        }
        __syncthreads();

        // recompute this segment's max
        float nv = (t < 100) ? scores[seg * 100 + t] : -1e30f;
        rv[t] = nv;
        __syncthreads();
        for (int s = 128; s > 0; s >>= 1) {
            if (t < s) rv[t] = fmaxf(rv[t], rv[t + s]);
            __syncthreads();
        }
        if (t == 0) smax[seg] = rv[0];
        __syncthreads();
    }

    // decode boxes
    if (t < 100) {
        const int g   = tIdx[t];
        const int ai  = g / 20;
        lab[t]        = g - ai * 20;
        const int pix = ai / 5;
        const int a   = ai - pix * 5;
        const float gx = (float)(pix % FMP);
        const float gy = (float)(pix / FMP);
        const float r0 = pred[(size_t)(105 + a * 4 + 0) * NPIX + pix];
        const float r1 = pred[(size_t)(105 + a * 4 + 1) * NPIX + pix];
        const float r2 = pred[(size_t)(105 + a * 4 + 2) * NPIX + pix];
        const float r3 = pred[(size_t)(105 + a * 4 + 3) * NPIX + pix];
        const float cx = (1.f / (1.f + expf(-r0)) + gx) * 32.f;
        const float cy = (1.f / (1.f + expf(-r1)) + gy) * 32.f;
        const float w  = expf(r2) * c_aw[a] * 32.f;
        const float h  = expf(r3) * c_ah[a] * 32.f;
        bx1[t] = cx - 0.5f * w; by1[t] = cy - 0.5f * h;
        bx2[t] = cx + 0.5f * w; by2[t] = cy + 0.5f * h;
        bar[t] = (bx2[t] - bx1[t]) * (by2[t] - by1[t]);
        keep[t] = (tScore[t] > 0.001f) ? 1 : 0;
    }
    __syncthreads();

    // greedy class-aware NMS, exact reference semantics
    for (int i = 0; i < 100; i++) {
        if (t < 100 && t > i && keep[i] && keep[t] && lab[t] == lab[i]) {
            const float xx1 = fmaxf(bx1[i], bx1[t]);
            const float yy1 = fmaxf(by1[i], by1[t]);
            const float xx2 = fminf(bx2[i], bx2[t]);
            const float yy2 = fminf(by2[i], by2[t]);
            const float inter = fmaxf(1e-10f, xx2 - xx1) * fmaxf(1e-10f, yy2 - yy1);
            const float iou = inter / (bar[i] + bar[t] - inter);
            if (iou > 0.6f) keep[t] = 0;
        }
        __syncthreads();
    }

    // outputs: bboxes(100x4), scores(100), labels(100), keep(100) -> 700 floats
    if (t < 100) {
        const bool k = keep[t] != 0;
        float o0 = 0.f, o1 = 0.f, o2 = 0.f, o3 = 0.f;
        if (k) {
            o0 = fminf(fmaxf(bx1[t] * (1.f / 1280.f), 0.f), 1.f);
            o1 = fminf(fmaxf(by1[t] * (1.f / 1280.f), 0.f), 1.f);
            o2 = fminf(fmaxf(bx2[t] * (1.f / 1280.f), 0.f), 1.f);
            o3 = fminf(fmaxf(by2[t] * (1.f / 1280.f), 0.f), 1.f);
        }
        out[t * 4 + 0] = o0; out[t * 4 + 1] = o1;
        out[t * 4 + 2] = o2; out[t * 4 + 3] = o3;
        out[400 + t] = k ? tScore[t] : 0.f;
        out[500 + t] = k ? (float)lab[t] : -1.f;
        out[600 + t] = k ? 1.f : 0.f;
    }
}

// ---------------- launch ----------------
extern "C" void kernel_launch(void* const* d_in, const int* in_sizes, int n_in,
                              void* d_out, int out_size)
{
    const float* c4  = (const float*)d_in[0];
    const float* c5  = (const float*)d_in[1];
    const float* w1a = (const float*)d_in[2];
    const float* s1a = (const float*)d_in[3];
    const float* b1a = (const float*)d_in[4];
    const float* w1b = (const float*)d_in[5];
    const float* s1b = (const float*)d_in[6];
    const float* b1b = (const float*)d_in[7];
    const float* wr  = (const float*)d_in[8];
    const float* sr  = (const float*)d_in[9];
    const float* br  = (const float*)d_in[10];
    const float* w2  = (const float*)d_in[11];
    const float* s2  = (const float*)d_in[12];
    const float* b2  = (const float*)d_in[13];
    const float* wp  = (const float*)d_in[14];
    const float* bp  = (const float*)d_in[15];

    float *padA, *padB, *padC, *p5b, *pred, *scores, *segmax;
    cudaGetSymbolAddress((void**)&padA,   g_padA);
    cudaGetSymbolAddress((void**)&padB,   g_padB);
    cudaGetSymbolAddress((void**)&padC,   g_padC);
    cudaGetSymbolAddress((void**)&p5b,    g_p5b);
    cudaGetSymbolAddress((void**)&pred,   g_pred);
    cudaGetSymbolAddress((void**)&scores, g_scores);
    cudaGetSymbolAddress((void**)&segmax, g_segmax);

    // zero padded buffers (borders must be 0; interiors are overwritten)
    cudaMemsetAsync(padA, 0, sizeof(float) * 1024 * PADPP);
    cudaMemsetAsync(padB, 0, sizeof(float) * 1024 * PADPP);
    cudaMemsetAsync(padC, 0, sizeof(float) * 1280 * PADPP);

    pad_input<<<(1024 * NPIX + 255) / 256, 256>>>(c5, padA, 1024);

    dim3 cgrid(25, 16);
    conv3x3_gemm<<<cgrid, 64>>>(w1a, padA, 1024, s1a, b1a, nullptr, padB, 0);
    conv3x3_gemm<<<cgrid, 64>>>(w1b, padB, 1024, s1b, b1b, nullptr, padC, 256);
    reorg_conv<<<1600, 256>>>(c4, wr, sr, br, padC);
    conv3x3_gemm<<<cgrid, 64>>>(w2, padC, 1280, s2, b2, p5b, nullptr, 0);
    pred_conv<<<800, 256>>>(p5b, wp, bp, pred);
    score_kernel<<<1600, 128>>>(pred, scores, segmax);
    finalize_kernel<<<1, 256>>>(scores, segmax, pred, (float*)d_out);
}

// round 2
// speedup vs baseline: 1.7822x; 1.7822x over previous
#include <cuda_runtime.h>
#include <cuda_bf16.h>
#include <cstdint>

// ---------------- static scratch (no allocations allowed) ----------------
#define FMP   40
#define NPIX  1600            // 40*40
#define PADW  42
#define PADPP 1764            // 42*42

__device__ float g_padA[1024 * PADPP];   // padded c5
__device__ float g_padB[1024 * PADPP];   // padded conv1 out
__device__ float g_padC[1280 * PADPP];   // padded concat (reorg 0..255, conv2 256..1279)
__device__ float g_p5b [1024 * NPIX];    // conv3 out (plain)
__device__ float g_pred[ 125 * NPIX];    // pred conv out
__device__ float g_scores[160000];       // 1600 px * 100
__device__ float g_segmax[1600];

__constant__ float c_aw[5] = {1.19f, 2.79f, 4.53f, 8.06f, 10.32f};
__constant__ float c_ah[5] = {1.98f, 4.59f, 8.92f, 5.29f, 10.65f};

// ---------------- packed fp32 FMA (sm_103a f32x2) ----------------
__device__ __forceinline__ void ffma2(float2& d, const float2& a, const float2& b) {
    unsigned long long&       du = reinterpret_cast<unsigned long long&>(d);
    const unsigned long long& au = reinterpret_cast<const unsigned long long&>(a);
    const unsigned long long& bu = reinterpret_cast<const unsigned long long&>(b);
    asm("fma.rn.f32x2 %0, %1, %2, %0;" : "+l"(du) : "l"(au), "l"(bu));
}

// ---------------- pad copy: (C,40,40) -> (C,42,42) interior ----------------
__global__ void pad_input(const float* __restrict__ src, float* __restrict__ dst, int C) {
    int idx = blockIdx.x * 256 + threadIdx.x;
    if (idx >= C * NPIX) return;
    int c = idx / NPIX, p = idx - c * NPIX;
    int y = p / FMP, x = p - y * FMP;
    dst[c * PADPP + (y + 1) * PADW + (x + 1)] = src[idx];
}

// ---------------- shared GEMM micro-kernel pieces ----------------
// 64 threads, BM=BN=64, BK=16, 8x8 outputs/thread as float2 pairs on m.

struct Frag { float2 acc[4][8]; };

__device__ __forceinline__ void frag_zero(Frag& f) {
    #pragma unroll
    for (int q = 0; q < 4; q++)
        #pragma unroll
        for (int j = 0; j < 8; j++) f.acc[q][j] = make_float2(0.f, 0.f);
}

__device__ __forceinline__ void gemm_compute(
    Frag& f, const float (*As)[64], const float (*Bs)[64], int tm, int tn)
{
    #pragma unroll
    for (int kk = 0; kk < 16; kk++) {
        const float4 a0 = *reinterpret_cast<const float4*>(&As[kk][tm * 8]);
        const float4 a1 = *reinterpret_cast<const float4*>(&As[kk][tm * 8 + 4]);
        const float4 b0 = *reinterpret_cast<const float4*>(&Bs[kk][tn * 8]);
        const float4 b1 = *reinterpret_cast<const float4*>(&Bs[kk][tn * 8 + 4]);
        float2 ap[4] = { make_float2(a0.x, a0.y), make_float2(a0.z, a0.w),
                         make_float2(a1.x, a1.y), make_float2(a1.z, a1.w) };
        float  bv[8] = { b0.x, b0.y, b0.z, b0.w, b1.x, b1.y, b1.z, b1.w };
        #pragma unroll
        for (int j = 0; j < 8; j++) {
            const float2 bb = make_float2(bv[j], bv[j]);
            #pragma unroll
            for (int q = 0; q < 4; q++) ffma2(f.acc[q][j], ap[q], bb);
        }
    }
}

// ---------------- 3x3 conv as implicit GEMM, double-buffered -----------------
// out[oc][p] = lrelu(scale[oc]*sum + shift[oc]); M=1024, N=1600, K=Cin*9
__global__ void __launch_bounds__(64, 4) conv3x3_gemm(
    const float* __restrict__ W, const float* __restrict__ padIn, int Cin,
    const float* __restrict__ scale, const float* __restrict__ shift,
    float* __restrict__ outPlain, float* __restrict__ outPad, int chanOff)
{
    __shared__ float As[2][16][64];
    __shared__ float Bs[2][16][64];

    const int t  = threadIdx.x;          // 0..63
    const int m0 = blockIdx.y * 64;
    const int n0 = blockIdx.x * 64;
    const int K  = Cin * 9;
    const int niter = K / 16;

    // B-load state (implicit im2col), advances 16 per fetch
    const int nn = t;
    const int p  = n0 + nn;
    const int py = p / FMP, px = p - py * FMP;
    const float* bsrc = padIn + (py * PADW + px);
    int icoff = 0, r = 0, roff = 0;

    const int tm = t >> 3;
    const int tn = t & 7;

    float4 rA[4];
    float  rB[16];

    // fetch tile i into registers
    auto fetchA = [&](int k0) {
        #pragma unroll
        for (int u = 0; u < 4; u++) {
            int idx = t + 64 * u;
            int mm  = idx >> 2;
            int kk4 = (idx & 3) << 2;
            rA[u] = *reinterpret_cast<const float4*>(W + (size_t)(m0 + mm) * K + (k0 + kk4));
        }
    };
    auto fetchB = [&]() {
        #pragma unroll
        for (int j = 0; j < 16; j++) {
            rB[j] = bsrc[icoff + roff];
            r++; roff++;
            if (r == 9)                { r = 0; roff = 0; icoff += PADPP; }
            else if (r == 3 || r == 6) { roff += 39; }
        }
    };
    auto store = [&](int buf) {
        #pragma unroll
        for (int u = 0; u < 4; u++) {
            int idx = t + 64 * u;
            int mm  = idx >> 2;
            int kk4 = (idx & 3) << 2;
            As[buf][kk4 + 0][mm] = rA[u].x; As[buf][kk4 + 1][mm] = rA[u].y;
            As[buf][kk4 + 2][mm] = rA[u].z; As[buf][kk4 + 3][mm] = rA[u].w;
        }
        #pragma unroll
        for (int j = 0; j < 16; j++) Bs[buf][j][nn] = rB[j];
    };

    Frag f; frag_zero(f);

    fetchA(0); fetchB();
    store(0);
    __syncthreads();

    for (int i = 0; i < niter; i++) {
        const int cur = i & 1;
        const bool more = (i + 1 < niter);
        if (more) { fetchA((i + 1) * 16); fetchB(); }   // LDG in flight during compute
        gemm_compute(f, As[cur], Bs[cur], tm, tn);
        if (more) {
            store(cur ^ 1);
            __syncthreads();
        }
    }

    // epilogue: BN + leaky ReLU
    #pragma unroll
    for (int q = 0; q < 4; q++) {
        #pragma unroll
        for (int h = 0; h < 2; h++) {
            const int oc = m0 + tm * 8 + q * 2 + h;
            const float sc = scale[oc], sh = shift[oc];
            #pragma unroll
            for (int j = 0; j < 8; j++) {
                float v = (h ? f.acc[q][j].y : f.acc[q][j].x);
                v = v * sc + sh;
                v = v > 0.f ? v : 0.1f * v;
                const int pp = n0 + tn * 8 + j;
                if (outPad) {
                    int y = pp / FMP, x = pp - y * FMP;
                    outPad[(size_t)(chanOff + oc) * PADPP + (y + 1) * PADW + (x + 1)] = v;
                } else {
                    outPlain[(size_t)oc * NPIX + pp] = v;
                }
            }
        }
    }
}

// ---------------- plain GEMM (B = dense [K][N]), double-buffered -------------
// mode 2: BN+lrelu + reorg scatter (M=64, N=6400) -> padC channels 0..255
// mode 3: bias only -> pred plain (M=125, N=1600)
__global__ void __launch_bounds__(64, 4) plain_gemm(
    const float* __restrict__ A, const float* __restrict__ B,
    int M, int N, int K,
    const float* __restrict__ scale, const float* __restrict__ shift,
    float* __restrict__ out, int mode)
{
    __shared__ float As[2][16][64];
    __shared__ float Bs[2][16][64];

    const int t  = threadIdx.x;
    const int m0 = blockIdx.y * 64;
    const int n0 = blockIdx.x * 64;
    const int niter = K / 16;
    const int nn = t;
    const int tm = t >> 3;
    const int tn = t & 7;

    float4 rA[4];
    float  rB[16];

    auto fetchA = [&](int k0) {
        #pragma unroll
        for (int u = 0; u < 4; u++) {
            int idx = t + 64 * u;
            int mm  = idx >> 2;
            int kk4 = (idx & 3) << 2;
            int row = m0 + mm; if (row >= M) row = M - 1;
            rA[u] = *reinterpret_cast<const float4*>(A + (size_t)row * K + (k0 + kk4));
        }
    };
    auto fetchB = [&](int k0) {
        #pragma unroll
        for (int j = 0; j < 16; j++)
            rB[j] = B[(size_t)(k0 + j) * N + n0 + nn];
    };
    auto store = [&](int buf) {
        #pragma unroll
        for (int u = 0; u < 4; u++) {
            int idx = t + 64 * u;
            int mm  = idx >> 2;
            int kk4 = (idx & 3) << 2;
            As[buf][kk4 + 0][mm] = rA[u].x; As[buf][kk4 + 1][mm] = rA[u].y;
            As[buf][kk4 + 2][mm] = rA[u].z; As[buf][kk4 + 3][mm] = rA[u].w;
        }
        #pragma unroll
        for (int j = 0; j < 16; j++) Bs[buf][j][nn] = rB[j];
    };

    Frag f; frag_zero(f);
    fetchA(0); fetchB(0);
    store(0);
    __syncthreads();

    for (int i = 0; i < niter; i++) {
        const int cur = i & 1;
        const bool more = (i + 1 < niter);
        if (more) { fetchA((i + 1) * 16); fetchB((i + 1) * 16); }
        gemm_compute(f, As[cur], Bs[cur], tm, tn);
        if (more) {
            store(cur ^ 1);
            __syncthreads();
        }
    }

    #pragma unroll
    for (int q = 0; q < 4; q++) {
        #pragma unroll
        for (int h = 0; h < 2; h++) {
            const int oc = m0 + tm * 8 + q * 2 + h;
            if (oc >= M) continue;
            #pragma unroll
            for (int j = 0; j < 8; j++) {
                float v = (h ? f.acc[q][j].y : f.acc[q][j].x);
                const int pp = n0 + tn * 8 + j;
                if (mode == 2) {
                    v = v * scale[oc] + shift[oc];
                    v = v > 0.f ? v : 0.1f * v;
                    const int y80 = pp / 80, x80 = pp - y80 * 80;
                    const int q4  = (y80 & 1) * 2 + (x80 & 1);
                    out[(size_t)(q4 * 64 + oc) * PADPP
                        + ((y80 >> 1) + 1) * PADW + ((x80 >> 1) + 1)] = v;
                } else { // mode 3: bias only
                    out[(size_t)oc * NPIX + pp] = v + shift[oc];
                }
            }
        }
    }
}

// ---------------- scores: sigmoid(conf)*softmax(cls) + segment max ----------
__global__ void __launch_bounds__(128) score_kernel(
    const float* __restrict__ pred, float* __restrict__ scores,
    float* __restrict__ segmax)
{
    const int p = blockIdx.x;
    const int t = threadIdx.x;
    __shared__ float sv[125];
    __shared__ float red[128];
    if (t < 125) sv[t] = pred[(size_t)t * NPIX + p];
    __syncthreads();

    float sc = -1.0f;
    if (t < 100) {
        const int a = t / 20, c = t - (t / 20) * 20;
        const float* cb = &sv[5 + a * 20];
        float m = cb[0];
        #pragma unroll
        for (int k = 1; k < 20; k++) m = fmaxf(m, cb[k]);
        float sum = 0.f;
        #pragma unroll
        for (int k = 0; k < 20; k++) sum += expf(cb[k] - m);
        const float e   = expf(cb[c] - m);
        const float sig = 1.f / (1.f + expf(-sv[a]));
        sc = sig * (e / sum);
        scores[p * 100 + t] = sc;
    }
    red[t] = sc;
    __syncthreads();
    for (int s = 64; s > 0; s >>= 1) {
        if (t < s) red[t] = fmaxf(red[t], red[t + s]);
        __syncthreads();
    }
    if (t == 0) segmax[p] = red[0];
}

// ---------------- top-100 + decode + greedy NMS + outputs (one block) ------
__global__ void __launch_bounds__(256) finalize_kernel(
    float* __restrict__ scores, const float* __restrict__ segmax_g,
    const float* __restrict__ pred, float* __restrict__ out)
{
    __shared__ float smax[1600];
    __shared__ float rv[256];
    __shared__ int   ri[256];
    __shared__ float tScore[100];
    __shared__ int   tIdx[100];
    __shared__ float bx1[100], by1[100], bx2[100], by2[100], bar[100];
    __shared__ int   lab[100];
    __shared__ int   keep[100];

    const int t = threadIdx.x;
    for (int i = t; i < 1600; i += 256) smax[i] = segmax_g[i];
    __syncthreads();

    for (int it = 0; it < 100; it++) {
        float bv = -1e30f; int bi = 1 << 30;
        for (int i = t; i < 1600; i += 256) {
            float v = smax[i];
            if (v > bv) { bv = v; bi = i; }
        }
        rv[t] = bv; ri[t] = bi;
        __syncthreads();
        for (int s = 128; s > 0; s >>= 1) {
            if (t < s) {
                float v2 = rv[t + s]; int i2 = ri[t + s];
                if (v2 > rv[t] || (v2 == rv[t] && i2 < ri[t])) { rv[t] = v2; ri[t] = i2; }
            }
            __syncthreads();
        }
        const int seg = ri[0];
        __syncthreads();

        float ev = -1e30f; int ei = 1 << 30;
        if (t < 100) { ev = scores[seg * 100 + t]; ei = t; }
        rv[t] = ev; ri[t] = ei;
        __syncthreads();
        for (int s = 128; s > 0; s >>= 1) {
            if (t < s) {
                float v2 = rv[t + s]; int i2 = ri[t + s];
                if (v2 > rv[t] || (v2 == rv[t] && i2 < ri[t])) { rv[t] = v2; ri[t] = i2; }
            }
            __syncthreads();
        }
        if (t == 0) {
            const int g = seg * 100 + ri[0];
            tIdx[it] = g; tScore[it] = rv[0];
            scores[g] = -1.0f;
        }
        __syncthreads();

        float nv = (t < 100) ? scores[seg * 100 + t] : -1e30f;
        rv[t] = nv;
        __syncthreads();
        for (int s = 128; s > 0; s >>= 1) {
            if (t < s) rv[t] = fmaxf(rv[t], rv[t + s]);
            __syncthreads();
        }
        if (t == 0) smax[seg] = rv[0];
        __syncthreads();
    }

    if (t < 100) {
        const int g   = tIdx[t];
        const int ai  = g / 20;
        lab[t]        = g - ai * 20;
        const int pix = ai / 5;
        const int a   = ai - pix * 5;
        const float gx = (float)(pix % FMP);
        const float gy = (float)(pix / FMP);
        const float r0 = pred[(size_t)(105 + a * 4 + 0) * NPIX + pix];
        const float r1 = pred[(size_t)(105 + a * 4 + 1) * NPIX + pix];
        const float r2 = pred[(size_t)(105 + a * 4 + 2) * NPIX + pix];
        const float r3 = pred[(size_t)(105 + a * 4 + 3) * NPIX + pix];
        const float cx = (1.f / (1.f + expf(-r0)) + gx) * 32.f;
        const float cy = (1.f / (1.f + expf(-r1)) + gy) * 32.f;
        const float w  = expf(r2) * c_aw[a] * 32.f;
        const float h  = expf(r3) * c_ah[a] * 32.f;
        bx1[t] = cx - 0.5f * w; by1[t] = cy - 0.5f * h;
        bx2[t] = cx + 0.5f * w; by2[t] = cy + 0.5f * h;
        bar[t] = (bx2[t] - bx1[t]) * (by2[t] - by1[t]);
        keep[t] = (tScore[t] > 0.001f) ? 1 : 0;
    }
    __syncthreads();

    for (int i = 0; i < 100; i++) {
        if (t < 100 && t > i && keep[i] && keep[t] && lab[t] == lab[i]) {
            const float xx1 = fmaxf(bx1[i], bx1[t]);
            const float yy1 = fmaxf(by1[i], by1[t]);
            const float xx2 = fminf(bx2[i], bx2[t]);
            const float yy2 = fminf(by2[i], by2[t]);
            const float inter = fmaxf(1e-10f, xx2 - xx1) * fmaxf(1e-10f, yy2 - yy1);
            const float iou = inter / (bar[i] + bar[t] - inter);
            if (iou > 0.6f) keep[t] = 0;
        }
        __syncthreads();
    }

    if (t < 100) {
        const bool k = keep[t] != 0;
        float o0 = 0.f, o1 = 0.f, o2 = 0.f, o3 = 0.f;
        if (k) {
            o0 = fminf(fmaxf(bx1[t] * (1.f / 1280.f), 0.f), 1.f);
            o1 = fminf(fmaxf(by1[t] * (1.f / 1280.f), 0.f), 1.f);
            o2 = fminf(fmaxf(bx2[t] * (1.f / 1280.f), 0.f), 1.f);
            o3 = fminf(fmaxf(by2[t] * (1.f / 1280.f), 0.f), 1.f);
        }
        out[t * 4 + 0] = o0; out[t * 4 + 1] = o1;
        out[t * 4 + 2] = o2; out[t * 4 + 3] = o3;
        out[400 + t] = k ? tScore[t] : 0.f;
        out[500 + t] = k ? (float)lab[t] : -1.f;
        out[600 + t] = k ? 1.f : 0.f;
    }
}

// ---------------- launch ----------------
extern "C" void kernel_launch(void* const* d_in, const int* in_sizes, int n_in,
                              void* d_out, int out_size)
{
    const float* c4  = (const float*)d_in[0];
    const float* c5  = (const float*)d_in[1];
    const float* w1a = (const float*)d_in[2];
    const float* s1a = (const float*)d_in[3];
    const float* b1a = (const float*)d_in[4];
    const float* w1b = (const float*)d_in[5];
    const float* s1b = (const float*)d_in[6];
    const float* b1b = (const float*)d_in[7];
    const float* wr  = (const float*)d_in[8];
    const float* sr  = (const float*)d_in[9];
    const float* br  = (const float*)d_in[10];
    const float* w2  = (const float*)d_in[11];
    const float* s2  = (const float*)d_in[12];
    const float* b2  = (const float*)d_in[13];
    const float* wp  = (const float*)d_in[14];
    const float* bp  = (const float*)d_in[15];

    float *padA, *padB, *padC, *p5b, *pred, *scores, *segmax;
    cudaGetSymbolAddress((void**)&padA,   g_padA);
    cudaGetSymbolAddress((void**)&padB,   g_padB);
    cudaGetSymbolAddress((void**)&padC,   g_padC);
    cudaGetSymbolAddress((void**)&p5b,    g_p5b);
    cudaGetSymbolAddress((void**)&pred,   g_pred);
    cudaGetSymbolAddress((void**)&scores, g_scores);
    cudaGetSymbolAddress((void**)&segmax, g_segmax);

    cudaMemsetAsync(padA, 0, sizeof(float) * 1024 * PADPP);
    cudaMemsetAsync(padB, 0, sizeof(float) * 1024 * PADPP);
    cudaMemsetAsync(padC, 0, sizeof(float) * 1280 * PADPP);

    pad_input<<<(1024 * NPIX + 255) / 256, 256>>>(c5, padA, 1024);

    dim3 cgrid(25, 16);
    conv3x3_gemm<<<cgrid, 64>>>(w1a, padA, 1024, s1a, b1a, nullptr, padB, 0);
    conv3x3_gemm<<<cgrid, 64>>>(w1b, padB, 1024, s1b, b1b, nullptr, padC, 256);
    // reorg: A=wr (64x512), B=c4 (512x6400) -> scatter into padC ch 0..255
    plain_gemm<<<dim3(100, 1), 64>>>(wr, c4, 64, 6400, 512, sr, br, padC, 2);
    conv3x3_gemm<<<cgrid, 64>>>(w2, padC, 1280, s2, b2, p5b, nullptr, 0);
    // pred: A=wp (125x1024), B=p5b (1024x1600) -> g_pred, bias only
    plain_gemm<<<dim3(25, 2), 64>>>(wp, p5b, 125, 1600, 1024, nullptr, bp, pred, 3);
    score_kernel<<<1600, 128>>>(pred, scores, segmax);
    finalize_kernel<<<1, 256>>>(scores, segmax, pred, (float*)d_out);
}

// round 3
// speedup vs baseline: 2.1957x; 1.2320x over previous
#include <cuda_runtime.h>
#include <cuda_bf16.h>
#include <cstdint>

// ---------------- static scratch (no allocations allowed) ----------------
#define FMP   40
#define NPIX  1600            // 40*40
#define PADW  42
#define PADPP 1764            // 42*42

__device__ float g_padA[1024 * PADPP];   // padded c5
__device__ float g_padB[1024 * PADPP];   // padded conv1 out
__device__ float g_padC[1280 * PADPP];   // padded concat (reorg 0..255, conv2 256..1279)
__device__ float g_p5b [1024 * NPIX];    // conv3 out (plain)
__device__ float g_pred[ 125 * NPIX];    // pred conv out
__device__ float g_scores[160000];       // 1600 px * 100
__device__ float g_segmax[1600];

__constant__ float c_aw[5] = {1.19f, 2.79f, 4.53f, 8.06f, 10.32f};
__constant__ float c_ah[5] = {1.98f, 4.59f, 8.92f, 5.29f, 10.65f};
__constant__ int   c_roff[9] = {0, 1, 2, PADW, PADW + 1, PADW + 2,
                                2 * PADW, 2 * PADW + 1, 2 * PADW + 2};

// ---------------- packed fp32 FMA (sm_103a f32x2) ----------------
__device__ __forceinline__ void ffma2(float2& d, const float2& a, const float2& b) {
    unsigned long long&       du = reinterpret_cast<unsigned long long&>(d);
    const unsigned long long& au = reinterpret_cast<const unsigned long long&>(a);
    const unsigned long long& bu = reinterpret_cast<const unsigned long long&>(b);
    asm("fma.rn.f32x2 %0, %1, %2, %0;" : "+l"(du) : "l"(au), "l"(bu));
}

// ---------------- pad copy: (C,40,40) -> (C,42,42) interior ----------------
__global__ void pad_input(const float* __restrict__ src, float* __restrict__ dst, int C) {
    int idx = blockIdx.x * 256 + threadIdx.x;
    if (idx >= C * NPIX) return;
    int c = idx / NPIX, p = idx - c * NPIX;
    int y = p / FMP, x = p - y * FMP;
    dst[c * PADPP + (y + 1) * PADW + (x + 1)] = src[idx];
}

// =====================================================================
// GEMM core: BM=BN=64, BK=16, 128 threads (4 warps -> all 4 SMSPs).
// Split-K inside the block: group g = t>>6 computes kk in [g*8, g*8+8).
// Per-thread 8m x 8n outputs, m packed as float2 pairs. Double-buffered.
// Shared memory: sh[0..2047] = As[2][16][64], sh[2048..4095] = Bs[2][16][64];
// after the mainloop the same 16KB is reused as red[64][64] for the
// cross-group partial-sum combine.
// =====================================================================

struct Frag { float2 acc[4][8]; };

__device__ __forceinline__ void frag_zero(Frag& f) {
    #pragma unroll
    for (int q = 0; q < 4; q++)
        #pragma unroll
        for (int j = 0; j < 8; j++) f.acc[q][j] = make_float2(0.f, 0.f);
}

__device__ __forceinline__ void gemm_compute_half(
    Frag& f, const float* As, const float* Bs, int g, int tm, int tn)
{
    // As/Bs point at the current buffer: As[kk][64], Bs[kk][64]
    #pragma unroll
    for (int u = 0; u < 8; u++) {
        const int kk = g * 8 + u;
        const float4 a0 = *reinterpret_cast<const float4*>(&As[kk * 64 + tm * 8]);
        const float4 a1 = *reinterpret_cast<const float4*>(&As[kk * 64 + tm * 8 + 4]);
        const float4 b0 = *reinterpret_cast<const float4*>(&Bs[kk * 64 + tn * 8]);
        const float4 b1 = *reinterpret_cast<const float4*>(&Bs[kk * 64 + tn * 8 + 4]);
        float2 ap[4] = { make_float2(a0.x, a0.y), make_float2(a0.z, a0.w),
                         make_float2(a1.x, a1.y), make_float2(a1.z, a1.w) };
        float  bv[8] = { b0.x, b0.y, b0.z, b0.w, b1.x, b1.y, b1.z, b1.w };
        #pragma unroll
        for (int j = 0; j < 8; j++) {
            const float2 bb = make_float2(bv[j], bv[j]);
            #pragma unroll
            for (int q = 0; q < 4; q++) ffma2(f.acc[q][j], ap[q], bb);
        }
    }
}

// combine group-1 partials into group-0 acc via smem
__device__ __forceinline__ void splitk_combine(Frag& f, float* sh, int g, int tm, int tn)
{
    __syncthreads();
    if (g == 1) {
        #pragma unroll
        for (int q = 0; q < 4; q++) {
            float4 lo = make_float4(f.acc[q][0].x, f.acc[q][1].x, f.acc[q][2].x, f.acc[q][3].x);
            float4 lo2= make_float4(f.acc[q][4].x, f.acc[q][5].x, f.acc[q][6].x, f.acc[q][7].x);
            float4 hi = make_float4(f.acc[q][0].y, f.acc[q][1].y, f.acc[q][2].y, f.acc[q][3].y);
            float4 hi2= make_float4(f.acc[q][4].y, f.acc[q][5].y, f.acc[q][6].y, f.acc[q][7].y);
            const int m0l = tm * 8 + q * 2;
            *reinterpret_cast<float4*>(&sh[(m0l + 0) * 64 + tn * 8    ]) = lo;
            *reinterpret_cast<float4*>(&sh[(m0l + 0) * 64 + tn * 8 + 4]) = lo2;
            *reinterpret_cast<float4*>(&sh[(m0l + 1) * 64 + tn * 8    ]) = hi;
            *reinterpret_cast<float4*>(&sh[(m0l + 1) * 64 + tn * 8 + 4]) = hi2;
        }
    }
    __syncthreads();
    if (g == 0) {
        #pragma unroll
        for (int q = 0; q < 4; q++) {
            const int m0l = tm * 8 + q * 2;
            #pragma unroll
            for (int j = 0; j < 8; j++) {
                f.acc[q][j].x += sh[(m0l + 0) * 64 + tn * 8 + j];
                f.acc[q][j].y += sh[(m0l + 1) * 64 + tn * 8 + j];
            }
        }
    }
}

// ---------------- 3x3 conv as implicit GEMM ----------------
// out[oc][p] = lrelu(scale[oc]*sum + shift[oc]); M=1024, N=1600, K=Cin*9
__global__ void __launch_bounds__(128, 3) conv3x3_gemm(
    const float* __restrict__ W, const float* __restrict__ padIn, int Cin,
    const float* __restrict__ scale, const float* __restrict__ shift,
    float* __restrict__ outPlain, float* __restrict__ outPad, int chanOff)
{
    __shared__ float sh[4096];   // As[2][16][64] | Bs[2][16][64]
    float* As = sh;
    float* Bs = sh + 2048;

    const int t  = threadIdx.x;       // 0..127
    const int g  = t >> 6;            // split-K group
    const int tt = t & 63;
    const int tm = tt >> 3;
    const int tn = tt & 7;
    const int m0 = blockIdx.y * 64;
    const int n0 = blockIdx.x * 64;
    const int K  = Cin * 9;
    const int niter = K / 16;

    // B im2col base for this thread's column nn = tt... each thread loads 8 B
    // values: column nn = t & 63?? -> B tile is 16kk x 64nn; 128 threads load
    // 1024 values: thread handles nn = t&63, kk = (t>>6)*8 + j, j=0..7.
    const int nn = t & 63;
    const int p  = n0 + nn;
    const int py = p / FMP, px = p - py * FMP;
    const float* bsrc = padIn + (py * PADW + px);
    const int kbase = g * 8;          // this thread's kk offset within tile

    float4 rA[2];
    float  rB[8];

    auto fetchA = [&](int k0) {
        #pragma unroll
        for (int u = 0; u < 2; u++) {
            int idx = t + 128 * u;          // 0..255
            int mm  = idx >> 2;
            int kk4 = (idx & 3) << 2;
            rA[u] = *reinterpret_cast<const float4*>(W + (size_t)(m0 + mm) * K + (k0 + kk4));
        }
    };
    auto fetchB = [&](int k0) {
        #pragma unroll
        for (int j = 0; j < 8; j++) {
            int k  = k0 + kbase + j;
            int ic = k / 9;
            int r  = k - ic * 9;
            rB[j] = bsrc[ic * PADPP + c_roff[r]];
        }
    };
    auto store = [&](int buf) {
        float* A = As + buf * 1024;
        float* B = Bs + buf * 1024;
        #pragma unroll
        for (int u = 0; u < 2; u++) {
            int idx = t + 128 * u;
            int mm  = idx >> 2;
            int kk4 = (idx & 3) << 2;
            A[(kk4 + 0) * 64 + mm] = rA[u].x; A[(kk4 + 1) * 64 + mm] = rA[u].y;
            A[(kk4 + 2) * 64 + mm] = rA[u].z; A[(kk4 + 3) * 64 + mm] = rA[u].w;
        }
        #pragma unroll
        for (int j = 0; j < 8; j++) B[(kbase + j) * 64 + nn] = rB[j];
    };

    Frag f; frag_zero(f);
    fetchA(0); fetchB(0);
    store(0);
    __syncthreads();

    for (int i = 0; i < niter; i++) {
        const int cur = i & 1;
        const bool more = (i + 1 < niter);
        if (more) { fetchA((i + 1) * 16); fetchB((i + 1) * 16); }
        gemm_compute_half(f, As + cur * 1024, Bs + cur * 1024, g, tm, tn);
        if (more) { store(cur ^ 1); __syncthreads(); }
    }

    splitk_combine(f, sh, g, tm, tn);
    if (g != 0) return;

    // epilogue: BN + leaky ReLU
    #pragma unroll
    for (int q = 0; q < 4; q++) {
        #pragma unroll
        for (int h = 0; h < 2; h++) {
            const int oc = m0 + tm * 8 + q * 2 + h;
            const float sc = scale[oc], sh2 = shift[oc];
            #pragma unroll
            for (int j = 0; j < 8; j++) {
                float v = (h ? f.acc[q][j].y : f.acc[q][j].x);
                v = v * sc + sh2;
                v = v > 0.f ? v : 0.1f * v;
                const int pp = n0 + tn * 8 + j;
                if (outPad) {
                    int y = pp / FMP, x = pp - y * FMP;
                    outPad[(size_t)(chanOff + oc) * PADPP + (y + 1) * PADW + (x + 1)] = v;
                } else {
                    outPlain[(size_t)oc * NPIX + pp] = v;
                }
            }
        }
    }
}

// ---------------- plain GEMM (B dense [K][N]) ----------------
// mode 2: BN+lrelu + reorg scatter (M=64, N=6400) -> padC channels 0..255
// mode 3: bias only -> pred plain (M=125, N=1600)
__global__ void __launch_bounds__(128, 3) plain_gemm(
    const float* __restrict__ A_g, const float* __restrict__ B_g,
    int M, int N, int K,
    const float* __restrict__ scale, const float* __restrict__ shift,
    float* __restrict__ out, int mode)
{
    __shared__ float sh[4096];
    float* As = sh;
    float* Bs = sh + 2048;

    const int t  = threadIdx.x;
    const int g  = t >> 6;
    const int tt = t & 63;
    const int tm = tt >> 3;
    const int tn = tt & 7;
    const int m0 = blockIdx.y * 64;
    const int n0 = blockIdx.x * 64;
    const int niter = K / 16;
    const int nn = t & 63;
    const int kbase = g * 8;

    float4 rA[2];
    float  rB[8];

    auto fetchA = [&](int k0) {
        #pragma unroll
        for (int u = 0; u < 2; u++) {
            int idx = t + 128 * u;
            int mm  = idx >> 2;
            int kk4 = (idx & 3) << 2;
            int row = m0 + mm; if (row >= M) row = M - 1;
            rA[u] = *reinterpret_cast<const float4*>(A_g + (size_t)row * K + (k0 + kk4));
        }
    };
    auto fetchB = [&](int k0) {
        #pragma unroll
        for (int j = 0; j < 8; j++)
            rB[j] = B_g[(size_t)(k0 + kbase + j) * N + n0 + nn];
    };
    auto store = [&](int buf) {
        float* A = As + buf * 1024;
        float* B = Bs + buf * 1024;
        #pragma unroll
        for (int u = 0; u < 2; u++) {
            int idx = t + 128 * u;
            int mm  = idx >> 2;
            int kk4 = (idx & 3) << 2;
            A[(kk4 + 0) * 64 + mm] = rA[u].x; A[(kk4 + 1) * 64 + mm] = rA[u].y;
            A[(kk4 + 2) * 64 + mm] = rA[u].z; A[(kk4 + 3) * 64 + mm] = rA[u].w;
        }
        #pragma unroll
        for (int j = 0; j < 8; j++) B[(kbase + j) * 64 + nn] = rB[j];
    };

    Frag f; frag_zero(f);
    fetchA(0); fetchB(0);
    store(0);
    __syncthreads();

    for (int i = 0; i < niter; i++) {
        const int cur = i & 1;
        const bool more = (i + 1 < niter);
        if (more) { fetchA((i + 1) * 16); fetchB((i + 1) * 16); }
        gemm_compute_half(f, As + cur * 1024, Bs + cur * 1024, g, tm, tn);
        if (more) { store(cur ^ 1); __syncthreads(); }
    }

    splitk_combine(f, sh, g, tm, tn);
    if (g != 0) return;

    #pragma unroll
    for (int q = 0; q < 4; q++) {
        #pragma unroll
        for (int h = 0; h < 2; h++) {
            const int oc = m0 + tm * 8 + q * 2 + h;
            if (oc >= M) continue;
            #pragma unroll
            for (int j = 0; j < 8; j++) {
                float v = (h ? f.acc[q][j].y : f.acc[q][j].x);
                const int pp = n0 + tn * 8 + j;
                if (mode == 2) {
                    v = v * scale[oc] + shift[oc];
                    v = v > 0.f ? v : 0.1f * v;
                    const int y80 = pp / 80, x80 = pp - y80 * 80;
                    const int q4  = (y80 & 1) * 2 + (x80 & 1);
                    out[(size_t)(q4 * 64 + oc) * PADPP
                        + ((y80 >> 1) + 1) * PADW + ((x80 >> 1) + 1)] = v;
                } else { // mode 3: bias only
                    out[(size_t)oc * NPIX + pp] = v + shift[oc];
                }
            }
        }
    }
}

// ---------------- scores: sigmoid(conf)*softmax(cls) + segment max ----------
__global__ void __launch_bounds__(128) score_kernel(
    const float* __restrict__ pred, float* __restrict__ scores,
    float* __restrict__ segmax)
{
    const int p = blockIdx.x;
    const int t = threadIdx.x;
    __shared__ float sv[125];
    __shared__ float red[128];
    if (t < 125) sv[t] = pred[(size_t)t * NPIX + p];
    __syncthreads();

    float sc = -1.0f;
    if (t < 100) {
        const int a = t / 20, c = t - (t / 20) * 20;
        const float* cb = &sv[5 + a * 20];
        float m = cb[0];
        #pragma unroll
        for (int k = 1; k < 20; k++) m = fmaxf(m, cb[k]);
        float sum = 0.f;
        #pragma unroll
        for (int k = 0; k < 20; k++) sum += expf(cb[k] - m);
        const float e   = expf(cb[c] - m);
        const float sig = 1.f / (1.f + expf(-sv[a]));
        sc = sig * (e / sum);
        scores[p * 100 + t] = sc;
    }
    red[t] = sc;
    __syncthreads();
    for (int s = 64; s > 0; s >>= 1) {
        if (t < s) red[t] = fmaxf(red[t], red[t + s]);
        __syncthreads();
    }
    if (t == 0) segmax[p] = red[0];
}

// ---------------- top-100 + decode + greedy NMS + outputs (one block) ------
__global__ void __launch_bounds__(256) finalize_kernel(
    float* __restrict__ scores, const float* __restrict__ segmax_g,
    const float* __restrict__ pred, float* __restrict__ out)
{
    __shared__ float smax[1600];
    __shared__ float rv[256];
    __shared__ int   ri[256];
    __shared__ float tScore[100];
    __shared__ int   tIdx[100];
    __shared__ float bx1[100], by1[100], bx2[100], by2[100], bar[100];
    __shared__ int   lab[100];
    __shared__ int   keep[100];

    const int t = threadIdx.x;
    for (int i = t; i < 1600; i += 256) smax[i] = segmax_g[i];
    __syncthreads();

    for (int it = 0; it < 100; it++) {
        float bv = -1e30f; int bi = 1 << 30;
        for (int i = t; i < 1600; i += 256) {
            float v = smax[i];
            if (v > bv) { bv = v; bi = i; }
        }
        rv[t] = bv; ri[t] = bi;
        __syncthreads();
        for (int s = 128; s > 0; s >>= 1) {
            if (t < s) {
                float v2 = rv[t + s]; int i2 = ri[t + s];
                if (v2 > rv[t] || (v2 == rv[t] && i2 < ri[t])) { rv[t] = v2; ri[t] = i2; }
            }
            __syncthreads();
        }
        const int seg = ri[0];
        __syncthreads();

        float ev = -1e30f; int ei = 1 << 30;
        if (t < 100) { ev = scores[seg * 100 + t]; ei = t; }
        rv[t] = ev; ri[t] = ei;
        __syncthreads();
        for (int s = 128; s > 0; s >>= 1) {
            if (t < s) {
                float v2 = rv[t + s]; int i2 = ri[t + s];
                if (v2 > rv[t] || (v2 == rv[t] && i2 < ri[t])) { rv[t] = v2; ri[t] = i2; }
            }
            __syncthreads();
        }
        if (t == 0) {
            const int g = seg * 100 + ri[0];
            tIdx[it] = g; tScore[it] = rv[0];
            scores[g] = -1.0f;
        }
        __syncthreads();

        float nv = (t < 100) ? scores[seg * 100 + t] : -1e30f;
        rv[t] = nv;
        __syncthreads();
        for (int s = 128; s > 0; s >>= 1) {
            if (t < s) rv[t] = fmaxf(rv[t], rv[t + s]);
            __syncthreads();
        }
        if (t == 0) smax[seg] = rv[0];
        __syncthreads();
    }

    if (t < 100) {
        const int g   = tIdx[t];
        const int ai  = g / 20;
        lab[t]        = g - ai * 20;
        const int pix = ai / 5;
        const int a   = ai - pix * 5;
        const float gx = (float)(pix % FMP);
        const float gy = (float)(pix / FMP);
        const float r0 = pred[(size_t)(105 + a * 4 + 0) * NPIX + pix];
        const float r1 = pred[(size_t)(105 + a * 4 + 1) * NPIX + pix];
        const float r2 = pred[(size_t)(105 + a * 4 + 2) * NPIX + pix];
        const float r3 = pred[(size_t)(105 + a * 4 + 3) * NPIX + pix];
        const float cx = (1.f / (1.f + expf(-r0)) + gx) * 32.f;
        const float cy = (1.f / (1.f + expf(-r1)) + gy) * 32.f;
        const float w  = expf(r2) * c_aw[a] * 32.f;
        const float h  = expf(r3) * c_ah[a] * 32.f;
        bx1[t] = cx - 0.5f * w; by1[t] = cy - 0.5f * h;
        bx2[t] = cx + 0.5f * w; by2[t] = cy + 0.5f * h;
        bar[t] = (bx2[t] - bx1[t]) * (by2[t] - by1[t]);
        keep[t] = (tScore[t] > 0.001f) ? 1 : 0;
    }
    __syncthreads();

    for (int i = 0; i < 100; i++) {
        if (t < 100 && t > i && keep[i] && keep[t] && lab[t] == lab[i]) {
            const float xx1 = fmaxf(bx1[i], bx1[t]);
            const float yy1 = fmaxf(by1[i], by1[t]);
            const float xx2 = fminf(bx2[i], bx2[t]);
            const float yy2 = fminf(by2[i], by2[t]);
            const float inter = fmaxf(1e-10f, xx2 - xx1) * fmaxf(1e-10f, yy2 - yy1);
            const float iou = inter / (bar[i] + bar[t] - inter);
            if (iou > 0.6f) keep[t] = 0;
        }
        __syncthreads();
    }

    if (t < 100) {
        const bool k = keep[t] != 0;
        float o0 = 0.f, o1 = 0.f, o2 = 0.f, o3 = 0.f;
        if (k) {
            o0 = fminf(fmaxf(bx1[t] * (1.f / 1280.f), 0.f), 1.f);
            o1 = fminf(fmaxf(by1[t] * (1.f / 1280.f), 0.f), 1.f);
            o2 = fminf(fmaxf(bx2[t] * (1.f / 1280.f), 0.f), 1.f);
            o3 = fminf(fmaxf(by2[t] * (1.f / 1280.f), 0.f), 1.f);
        }
        out[t * 4 + 0] = o0; out[t * 4 + 1] = o1;
        out[t * 4 + 2] = o2; out[t * 4 + 3] = o3;
        out[400 + t] = k ? tScore[t] : 0.f;
        out[500 + t] = k ? (float)lab[t] : -1.f;
        out[600 + t] = k ? 1.f : 0.f;
    }
}

// ---------------- launch ----------------
extern "C" void kernel_launch(void* const* d_in, const int* in_sizes, int n_in,
                              void* d_out, int out_size)
{
    const float* c4  = (const float*)d_in[0];
    const float* c5  = (const float*)d_in[1];
    const float* w1a = (const float*)d_in[2];
    const float* s1a = (const float*)d_in[3];
    const float* b1a = (const float*)d_in[4];
    const float* w1b = (const float*)d_in[5];
    const float* s1b = (const float*)d_in[6];
    const float* b1b = (const float*)d_in[7];
    const float* wr  = (const float*)d_in[8];
    const float* sr  = (const float*)d_in[9];
    const float* br  = (const float*)d_in[10];
    const float* w2  = (const float*)d_in[11];
    const float* s2  = (const float*)d_in[12];
    const float* b2  = (const float*)d_in[13];
    const float* wp  = (const float*)d_in[14];
    const float* bp  = (const float*)d_in[15];

    float *padA, *padB, *padC, *p5b, *pred, *scores, *segmax;
    cudaGetSymbolAddress((void**)&padA,   g_padA);
    cudaGetSymbolAddress((void**)&padB,   g_padB);
    cudaGetSymbolAddress((void**)&padC,   g_padC);
    cudaGetSymbolAddress((void**)&p5b,    g_p5b);
    cudaGetSymbolAddress((void**)&pred,   g_pred);
    cudaGetSymbolAddress((void**)&scores, g_scores);
    cudaGetSymbolAddress((void**)&segmax, g_segmax);

    cudaMemsetAsync(padA, 0, sizeof(float) * 1024 * PADPP);
    cudaMemsetAsync(padB, 0, sizeof(float) * 1024 * PADPP);
    cudaMemsetAsync(padC, 0, sizeof(float) * 1280 * PADPP);

    pad_input<<<(1024 * NPIX + 255) / 256, 256>>>(c5, padA, 1024);

    dim3 cgrid(25, 16);
    conv3x3_gemm<<<cgrid, 128>>>(w1a, padA, 1024, s1a, b1a, nullptr, padB, 0);
    conv3x3_gemm<<<cgrid, 128>>>(w1b, padB, 1024, s1b, b1b, nullptr, padC, 256);
    // reorg: A=wr (64x512), B=c4 (512x6400) -> scatter into padC ch 0..255
    plain_gemm<<<dim3(100, 1), 128>>>(wr, c4, 64, 6400, 512, sr, br, padC, 2);
    conv3x3_gemm<<<cgrid, 128>>>(w2, padC, 1280, s2, b2, p5b, nullptr, 0);
    // pred: A=wp (125x1024), B=p5b (1024x1600) -> g_pred, bias only
    plain_gemm<<<dim3(25, 2), 128>>>(wp, p5b, 125, 1600, 1024, nullptr, bp, pred, 3);
    score_kernel<<<1600, 128>>>(pred, scores, segmax);
    finalize_kernel<<<1, 256>>>(scores, segmax, pred, (float*)d_out);
}

// round 4
// speedup vs baseline: 2.1961x; 1.0002x over previous
#include <cuda_runtime.h>
#include <cuda_bf16.h>
#include <cstdint>

// ---------------- static scratch (no allocations allowed) ----------------
#define FMP   40
#define NPIX  1600            // 40*40
#define PADW  42
#define PADPP 1764            // 42*42

__device__ float g_padA[1024 * PADPP];   // padded c5
__device__ float g_padB[1024 * PADPP];   // padded conv1 out
__device__ float g_padC[1280 * PADPP];   // padded concat (reorg 0..255, conv2 256..1279)
__device__ float g_p5b [1024 * NPIX];    // conv3 out (plain)
__device__ float g_pred[ 125 * NPIX];    // pred conv out
__device__ float g_scores[160000];       // 1600 px * 100
__device__ float g_segmax[1600];

__constant__ float c_aw[5] = {1.19f, 2.79f, 4.53f, 8.06f, 10.32f};
__constant__ float c_ah[5] = {1.98f, 4.59f, 8.92f, 5.29f, 10.65f};
__constant__ int   c_roff[9] = {0, 1, 2, PADW, PADW + 1, PADW + 2,
                                2 * PADW, 2 * PADW + 1, 2 * PADW + 2};

// ---------------- packed fp32 FMA (sm_103a f32x2) ----------------
__device__ __forceinline__ void ffma2(float2& d, const float2& a, const float2& b) {
    unsigned long long&       du = reinterpret_cast<unsigned long long&>(d);
    const unsigned long long& au = reinterpret_cast<const unsigned long long&>(a);
    const unsigned long long& bu = reinterpret_cast<const unsigned long long&>(b);
    asm("fma.rn.f32x2 %0, %1, %2, %0;" : "+l"(du) : "l"(au), "l"(bu));
}

// ---------------- pad copy: (C,40,40) -> (C,42,42) interior ----------------
__global__ void pad_input(const float* __restrict__ src, float* __restrict__ dst, int C) {
    int idx = blockIdx.x * 256 + threadIdx.x;
    if (idx >= C * NPIX) return;
    int c = idx / NPIX, p = idx - c * NPIX;
    int y = p / FMP, x = p - y * FMP;
    dst[c * PADPP + (y + 1) * PADW + (x + 1)] = src[idx];
}

// =====================================================================
// GEMM core: BM=BN=64, BK=16, 128 threads (4 warps -> all 4 SMSPs).
// Split-K inside the block: group g = t>>6 computes kk in [g*8, g*8+8).
// Per-thread 8m x 8n outputs, m packed as float2 pairs. Double-buffered.
// Shared memory: sh[0..2047] = As[2][16][64], sh[2048..4095] = Bs[2][16][64];
// after the mainloop the same 16KB is reused as red[64][64] for the
// cross-group partial-sum combine.
// =====================================================================

struct Frag { float2 acc[4][8]; };

__device__ __forceinline__ void frag_zero(Frag& f) {
    #pragma unroll
    for (int q = 0; q < 4; q++)
        #pragma unroll
        for (int j = 0; j < 8; j++) f.acc[q][j] = make_float2(0.f, 0.f);
}

__device__ __forceinline__ void gemm_compute_half(
    Frag& f, const float* As, const float* Bs, int g, int tm, int tn)
{
    // As/Bs point at the current buffer: As[kk][64], Bs[kk][64]
    #pragma unroll
    for (int u = 0; u < 8; u++) {
        const int kk = g * 8 + u;
        const float4 a0 = *reinterpret_cast<const float4*>(&As[kk * 64 + tm * 8]);
        const float4 a1 = *reinterpret_cast<const float4*>(&As[kk * 64 + tm * 8 + 4]);
        const float4 b0 = *reinterpret_cast<const float4*>(&Bs[kk * 64 + tn * 8]);
        const float4 b1 = *reinterpret_cast<const float4*>(&Bs[kk * 64 + tn * 8 + 4]);
        float2 ap[4] = { make_float2(a0.x, a0.y), make_float2(a0.z, a0.w),
                         make_float2(a1.x, a1.y), make_float2(a1.z, a1.w) };
        float  bv[8] = { b0.x, b0.y, b0.z, b0.w, b1.x, b1.y, b1.z, b1.w };
        #pragma unroll
        for (int j = 0; j < 8; j++) {
            const float2 bb = make_float2(bv[j], bv[j]);
            #pragma unroll
            for (int q = 0; q < 4; q++) ffma2(f.acc[q][j], ap[q], bb);
        }
    }
}

// combine group-1 partials into group-0 acc via smem
__device__ __forceinline__ void splitk_combine(Frag& f, float* sh, int g, int tm, int tn)
{
    __syncthreads();
    if (g == 1) {
        #pragma unroll
        for (int q = 0; q < 4; q++) {
            float4 lo = make_float4(f.acc[q][0].x, f.acc[q][1].x, f.acc[q][2].x, f.acc[q][3].x);
            float4 lo2= make_float4(f.acc[q][4].x, f.acc[q][5].x, f.acc[q][6].x, f.acc[q][7].x);
            float4 hi = make_float4(f.acc[q][0].y, f.acc[q][1].y, f.acc[q][2].y, f.acc[q][3].y);
            float4 hi2= make_float4(f.acc[q][4].y, f.acc[q][5].y, f.acc[q][6].y, f.acc[q][7].y);
            const int m0l = tm * 8 + q * 2;
            *reinterpret_cast<float4*>(&sh[(m0l + 0) * 64 + tn * 8    ]) = lo;
            *reinterpret_cast<float4*>(&sh[(m0l + 0) * 64 + tn * 8 + 4]) = lo2;
            *reinterpret_cast<float4*>(&sh[(m0l + 1) * 64 + tn * 8    ]) = hi;
            *reinterpret_cast<float4*>(&sh[(m0l + 1) * 64 + tn * 8 + 4]) = hi2;
        }
    }
    __syncthreads();
    if (g == 0) {
        #pragma unroll
        for (int q = 0; q < 4; q++) {
            const int m0l = tm * 8 + q * 2;
            #pragma unroll
            for (int j = 0; j < 8; j++) {
                f.acc[q][j].x += sh[(m0l + 0) * 64 + tn * 8 + j];
                f.acc[q][j].y += sh[(m0l + 1) * 64 + tn * 8 + j];
            }
        }
    }
}

// ---------------- 3x3 conv as implicit GEMM ----------------
// out[oc][p] = lrelu(scale[oc]*sum + shift[oc]); M=1024, N=1600, K=Cin*9
__global__ void __launch_bounds__(128, 3) conv3x3_gemm(
    const float* __restrict__ W, const float* __restrict__ padIn, int Cin,
    const float* __restrict__ scale, const float* __restrict__ shift,
    float* __restrict__ outPlain, float* __restrict__ outPad, int chanOff)
{
    __shared__ float sh[4096];   // As[2][16][64] | Bs[2][16][64]
    float* As = sh;
    float* Bs = sh + 2048;

    const int t  = threadIdx.x;       // 0..127
    const int g  = t >> 6;            // split-K group
    const int tt = t & 63;
    const int tm = tt >> 3;
    const int tn = tt & 7;
    const int m0 = blockIdx.y * 64;
    const int n0 = blockIdx.x * 64;
    const int K  = Cin * 9;
    const int niter = K / 16;

    // B im2col base for this thread's column nn = tt... each thread loads 8 B
    // values: column nn = t & 63?? -> B tile is 16kk x 64nn; 128 threads load
    // 1024 values: thread handles nn = t&63, kk = (t>>6)*8 + j, j=0..7.
    const int nn = t & 63;
    const int p  = n0 + nn;
    const int py = p / FMP, px = p - py * FMP;
    const float* bsrc = padIn + (py * PADW + px);
    const int kbase = g * 8;          // this thread's kk offset within tile

    float4 rA[2];
    float  rB[8];

    auto fetchA = [&](int k0) {
        #pragma unroll
        for (int u = 0; u < 2; u++) {
            int idx = t + 128 * u;          // 0..255
            int mm  = idx >> 2;
            int kk4 = (idx & 3) << 2;
            rA[u] = *reinterpret_cast<const float4*>(W + (size_t)(m0 + mm) * K + (k0 + kk4));
        }
    };
    auto fetchB = [&](int k0) {
        #pragma unroll
        for (int j = 0; j < 8; j++) {
            int k  = k0 + kbase + j;
            int ic = k / 9;
            int r  = k - ic * 9;
            rB[j] = bsrc[ic * PADPP + c_roff[r]];
        }
    };
    auto store = [&](int buf) {
        float* A = As + buf * 1024;
        float* B = Bs + buf * 1024;
        #pragma unroll
        for (int u = 0; u < 2; u++) {
            int idx = t + 128 * u;
            int mm  = idx >> 2;
            int kk4 = (idx & 3) << 2;
            A[(kk4 + 0) * 64 + mm] = rA[u].x; A[(kk4 + 1) * 64 + mm] = rA[u].y;
            A[(kk4 + 2) * 64 + mm] = rA[u].z; A[(kk4 + 3) * 64 + mm] = rA[u].w;
        }
        #pragma unroll
        for (int j = 0; j < 8; j++) B[(kbase + j) * 64 + nn] = rB[j];
    };

    Frag f; frag_zero(f);
    fetchA(0); fetchB(0);
    store(0);
    __syncthreads();

    for (int i = 0; i < niter; i++) {
        const int cur = i & 1;
        const bool more = (i + 1 < niter);
        if (more) { fetchA((i + 1) * 16); fetchB((i + 1) * 16); }
        gemm_compute_half(f, As + cur * 1024, Bs + cur * 1024, g, tm, tn);
        if (more) { store(cur ^ 1); __syncthreads(); }
    }

    splitk_combine(f, sh, g, tm, tn);
    if (g != 0) return;

    // epilogue: BN + leaky ReLU
    #pragma unroll
    for (int q = 0; q < 4; q++) {
        #pragma unroll
        for (int h = 0; h < 2; h++) {
            const int oc = m0 + tm * 8 + q * 2 + h;
            const float sc = scale[oc], sh2 = shift[oc];
            #pragma unroll
            for (int j = 0; j < 8; j++) {
                float v = (h ? f.acc[q][j].y : f.acc[q][j].x);
                v = v * sc + sh2;
                v = v > 0.f ? v : 0.1f * v;
                const int pp = n0 + tn * 8 + j;
                if (outPad) {
                    int y = pp / FMP, x = pp - y * FMP;
                    outPad[(size_t)(chanOff + oc) * PADPP + (y + 1) * PADW + (x + 1)] = v;
                } else {
                    outPlain[(size_t)oc * NPIX + pp] = v;
                }
            }
        }
    }
}

// ---------------- plain GEMM (B dense [K][N]) ----------------
// mode 2: BN+lrelu + reorg scatter (M=64, N=6400) -> padC channels 0..255
// mode 3: bias only -> pred plain (M=125, N=1600)
__global__ void __launch_bounds__(128, 3) plain_gemm(
    const float* __restrict__ A_g, const float* __restrict__ B_g,
    int M, int N, int K,
    const float* __restrict__ scale, const float* __restrict__ shift,
    float* __restrict__ out, int mode)
{
    __shared__ float sh[4096];
    float* As = sh;
    float* Bs = sh + 2048;

    const int t  = threadIdx.x;
    const int g  = t >> 6;
    const int tt = t & 63;
    const int tm = tt >> 3;
    const int tn = tt & 7;
    const int m0 = blockIdx.y * 64;
    const int n0 = blockIdx.x * 64;
    const int niter = K / 16;
    const int nn = t & 63;
    const int kbase = g * 8;

    float4 rA[2];
    float  rB[8];

    auto fetchA = [&](int k0) {
        #pragma unroll
        for (int u = 0; u < 2; u++) {
            int idx = t + 128 * u;
            int mm  = idx >> 2;
            int kk4 = (idx & 3) << 2;
            int row = m0 + mm; if (row >= M) row = M - 1;
            rA[u] = *reinterpret_cast<const float4*>(A_g + (size_t)row * K + (k0 + kk4));
        }
    };
    auto fetchB = [&](int k0) {
        #pragma unroll
        for (int j = 0; j < 8; j++)
            rB[j] = B_g[(size_t)(k0 + kbase + j) * N + n0 + nn];
    };
    auto store = [&](int buf) {
        float* A = As + buf * 1024;
        float* B = Bs + buf * 1024;
        #pragma unroll
        for (int u = 0; u < 2; u++) {
            int idx = t + 128 * u;
            int mm  = idx >> 2;
            int kk4 = (idx & 3) << 2;
            A[(kk4 + 0) * 64 + mm] = rA[u].x; A[(kk4 + 1) * 64 + mm] = rA[u].y;
            A[(kk4 + 2) * 64 + mm] = rA[u].z; A[(kk4 + 3) * 64 + mm] = rA[u].w;
        }
        #pragma unroll
        for (int j = 0; j < 8; j++) B[(kbase + j) * 64 + nn] = rB[j];
    };

    Frag f; frag_zero(f);
    fetchA(0); fetchB(0);
    store(0);
    __syncthreads();

    for (int i = 0; i < niter; i++) {
        const int cur = i & 1;
        const bool more = (i + 1 < niter);
        if (more) { fetchA((i + 1) * 16); fetchB((i + 1) * 16); }
        gemm_compute_half(f, As + cur * 1024, Bs + cur * 1024, g, tm, tn);
        if (more) { store(cur ^ 1); __syncthreads(); }
    }

    splitk_combine(f, sh, g, tm, tn);
    if (g != 0) return;

    #pragma unroll
    for (int q = 0; q < 4; q++) {
        #pragma unroll
        for (int h = 0; h < 2; h++) {
            const int oc = m0 + tm * 8 + q * 2 + h;
            if (oc >= M) continue;
            #pragma unroll
            for (int j = 0; j < 8; j++) {
                float v = (h ? f.acc[q][j].y : f.acc[q][j].x);
                const int pp = n0 + tn * 8 + j;
                if (mode == 2) {
                    v = v * scale[oc] + shift[oc];
                    v = v > 0.f ? v : 0.1f * v;
                    const int y80 = pp / 80, x80 = pp - y80 * 80;
                    const int q4  = (y80 & 1) * 2 + (x80 & 1);
                    out[(size_t)(q4 * 64 + oc) * PADPP
                        + ((y80 >> 1) + 1) * PADW + ((x80 >> 1) + 1)] = v;
                } else { // mode 3: bias only
                    out[(size_t)oc * NPIX + pp] = v + shift[oc];
                }
            }
        }
    }
}

// ---------------- scores: sigmoid(conf)*softmax(cls) + segment max ----------
__global__ void __launch_bounds__(128) score_kernel(
    const float* __restrict__ pred, float* __restrict__ scores,
    float* __restrict__ segmax)
{
    const int p = blockIdx.x;
    const int t = threadIdx.x;
    __shared__ float sv[125];
    __shared__ float red[128];
    if (t < 125) sv[t] = pred[(size_t)t * NPIX + p];
    __syncthreads();

    float sc = -1.0f;
    if (t < 100) {
        const int a = t / 20, c = t - (t / 20) * 20;
        const float* cb = &sv[5 + a * 20];
        float m = cb[0];
        #pragma unroll
        for (int k = 1; k < 20; k++) m = fmaxf(m, cb[k]);
        float sum = 0.f;
        #pragma unroll
        for (int k = 0; k < 20; k++) sum += expf(cb[k] - m);
        const float e   = expf(cb[c] - m);
        const float sig = 1.f / (1.f + expf(-sv[a]));
        sc = sig * (e / sum);
        scores[p * 100 + t] = sc;
    }
    red[t] = sc;
    __syncthreads();
    for (int s = 64; s > 0; s >>= 1) {
        if (t < s) red[t] = fmaxf(red[t], red[t + s]);
        __syncthreads();
    }
    if (t == 0) segmax[p] = red[0];
}

// ---------------- top-100 + decode + greedy NMS + outputs (one block) ------
__global__ void __launch_bounds__(256) finalize_kernel(
    float* __restrict__ scores, const float* __restrict__ segmax_g,
    const float* __restrict__ pred, float* __restrict__ out)
{
    __shared__ float smax[1600];
    __shared__ float rv[256];
    __shared__ int   ri[256];
    __shared__ float tScore[100];
    __shared__ int   tIdx[100];
    __shared__ float bx1[100], by1[100], bx2[100], by2[100], bar[100];
    __shared__ int   lab[100];
    __shared__ int   keep[100];

    const int t = threadIdx.x;
    for (int i = t; i < 1600; i += 256) smax[i] = segmax_g[i];
    __syncthreads();

    for (int it = 0; it < 100; it++) {
        float bv = -1e30f; int bi = 1 << 30;
        for (int i = t; i < 1600; i += 256) {
            float v = smax[i];
            if (v > bv) { bv = v; bi = i; }
        }
        rv[t] = bv; ri[t] = bi;
        __syncthreads();
        for (int s = 128; s > 0; s >>= 1) {
            if (t < s) {
                float v2 = rv[t + s]; int i2 = ri[t + s];
                if (v2 > rv[t] || (v2 == rv[t] && i2 < ri[t])) { rv[t] = v2; ri[t] = i2; }
            }
            __syncthreads();
        }
        const int seg = ri[0];
        __syncthreads();

        float ev = -1e30f; int ei = 1 << 30;
        if (t < 100) { ev = scores[seg * 100 + t]; ei = t; }
        rv[t] = ev; ri[t] = ei;
        __syncthreads();
        for (int s = 128; s > 0; s >>= 1) {
            if (t < s) {
                float v2 = rv[t + s]; int i2 = ri[t + s];
                if (v2 > rv[t] || (v2 == rv[t] && i2 < ri[t])) { rv[t] = v2; ri[t] = i2; }
            }
            __syncthreads();
        }
        if (t == 0) {
            const int g = seg * 100 + ri[0];
            tIdx[it] = g; tScore[it] = rv[0];
            scores[g] = -1.0f;
        }
        __syncthreads();

        float nv = (t < 100) ? scores[seg * 100 + t] : -1e30f;
        rv[t] = nv;
        __syncthreads();
        for (int s = 128; s > 0; s >>= 1) {
            if (t < s) rv[t] = fmaxf(rv[t], rv[t + s]);
            __syncthreads();
        }
        if (t == 0) smax[seg] = rv[0];
        __syncthreads();
    }

    if (t < 100) {
        const int g   = tIdx[t];
        const int ai  = g / 20;
        lab[t]        = g - ai * 20;
        const int pix = ai / 5;
        const int a   = ai - pix * 5;
        const float gx = (float)(pix % FMP);
        const float gy = (float)(pix / FMP);
        const float r0 = pred[(size_t)(105 + a * 4 + 0) * NPIX + pix];
        const float r1 = pred[(size_t)(105 + a * 4 + 1) * NPIX + pix];
        const float r2 = pred[(size_t)(105 + a * 4 + 2) * NPIX + pix];
        const float r3 = pred[(size_t)(105 + a * 4 + 3) * NPIX + pix];
        const float cx = (1.f / (1.f + expf(-r0)) + gx) * 32.f;
        const float cy = (1.f / (1.f + expf(-r1)) + gy) * 32.f;
        const float w  = expf(r2) * c_aw[a] * 32.f;
        const float h  = expf(r3) * c_ah[a] * 32.f;
        bx1[t] = cx - 0.5f * w; by1[t] = cy - 0.5f * h;
        bx2[t] = cx + 0.5f * w; by2[t] = cy + 0.5f * h;
        bar[t] = (bx2[t] - bx1[t]) * (by2[t] - by1[t]);
        keep[t] = (tScore[t] > 0.001f) ? 1 : 0;
    }
    __syncthreads();

    for (int i = 0; i < 100; i++) {
        if (t < 100 && t > i && keep[i] && keep[t] && lab[t] == lab[i]) {
            const float xx1 = fmaxf(bx1[i], bx1[t]);
            const float yy1 = fmaxf(by1[i], by1[t]);
            const float xx2 = fminf(bx2[i], bx2[t]);
            const float yy2 = fminf(by2[i], by2[t]);
            const float inter = fmaxf(1e-10f, xx2 - xx1) * fmaxf(1e-10f, yy2 - yy1);
            const float iou = inter / (bar[i] + bar[t] - inter);
            if (iou > 0.6f) keep[t] = 0;
        }
        __syncthreads();
    }

    if (t < 100) {
        const bool k = keep[t] != 0;
        float o0 = 0.f, o1 = 0.f, o2 = 0.f, o3 = 0.f;
        if (k) {
            o0 = fminf(fmaxf(bx1[t] * (1.f / 1280.f), 0.f), 1.f);
            o1 = fminf(fmaxf(by1[t] * (1.f / 1280.f), 0.f), 1.f);
            o2 = fminf(fmaxf(bx2[t] * (1.f / 1280.f), 0.f), 1.f);
            o3 = fminf(fmaxf(by2[t] * (1.f / 1280.f), 0.f), 1.f);
        }
        out[t * 4 + 0] = o0; out[t * 4 + 1] = o1;
        out[t * 4 + 2] = o2; out[t * 4 + 3] = o3;
        out[400 + t] = k ? tScore[t] : 0.f;
        out[500 + t] = k ? (float)lab[t] : -1.f;
        out[600 + t] = k ? 1.f : 0.f;
    }
}

// ---------------- launch ----------------
extern "C" void kernel_launch(void* const* d_in, const int* in_sizes, int n_in,
                              void* d_out, int out_size)
{
    const float* c4  = (const float*)d_in[0];
    const float* c5  = (const float*)d_in[1];
    const float* w1a = (const float*)d_in[2];
    const float* s1a = (const float*)d_in[3];
    const float* b1a = (const float*)d_in[4];
    const float* w1b = (const float*)d_in[5];
    const float* s1b = (const float*)d_in[6];
    const float* b1b = (const float*)d_in[7];
    const float* wr  = (const float*)d_in[8];
    const float* sr  = (const float*)d_in[9];
    const float* br  = (const float*)d_in[10];
    const float* w2  = (const float*)d_in[11];
    const float* s2  = (const float*)d_in[12];
    const float* b2  = (const float*)d_in[13];
    const float* wp  = (const float*)d_in[14];
    const float* bp  = (const float*)d_in[15];

    float *padA, *padB, *padC, *p5b, *pred, *scores, *segmax;
    cudaGetSymbolAddress((void**)&padA,   g_padA);
    cudaGetSymbolAddress((void**)&padB,   g_padB);
    cudaGetSymbolAddress((void**)&padC,   g_padC);
    cudaGetSymbolAddress((void**)&p5b,    g_p5b);
    cudaGetSymbolAddress((void**)&pred,   g_pred);
    cudaGetSymbolAddress((void**)&scores, g_scores);
    cudaGetSymbolAddress((void**)&segmax, g_segmax);

    cudaMemsetAsync(padA, 0, sizeof(float) * 1024 * PADPP);
    cudaMemsetAsync(padB, 0, sizeof(float) * 1024 * PADPP);
    cudaMemsetAsync(padC, 0, sizeof(float) * 1280 * PADPP);

    pad_input<<<(1024 * NPIX + 255) / 256, 256>>>(c5, padA, 1024);

    dim3 cgrid(25, 16);
    conv3x3_gemm<<<cgrid, 128>>>(w1a, padA, 1024, s1a, b1a, nullptr, padB, 0);
    conv3x3_gemm<<<cgrid, 128>>>(w1b, padB, 1024, s1b, b1b, nullptr, padC, 256);
    // reorg: A=wr (64x512), B=c4 (512x6400) -> scatter into padC ch 0..255
    plain_gemm<<<dim3(100, 1), 128>>>(wr, c4, 64, 6400, 512, sr, br, padC, 2);
    conv3x3_gemm<<<cgrid, 128>>>(w2, padC, 1280, s2, b2, p5b, nullptr, 0);
    // pred: A=wp (125x1024), B=p5b (1024x1600) -> g_pred, bias only
    plain_gemm<<<dim3(25, 2), 128>>>(wp, p5b, 125, 1600, 1024, nullptr, bp, pred, 3);
    score_kernel<<<1600, 128>>>(pred, scores, segmax);
    finalize_kernel<<<1, 256>>>(scores, segmax, pred, (float*)d_out);
}